// round 2
// baseline (speedup 1.0000x reference)
#include <cuda_runtime.h>
#include <cuda_bf16.h>

// q[i] = sum_j relu(neg[j] - pos[i] + DELTA)
//      = sum_j max(neg[j], t_i) - cnt * t_i,   t_i = pos[i] - DELTA   (per chunk)
// out[0..L)       = lambdas, then out[idx[i]] += mu*q[i]  (unique idx)
// out[out_size-1] = (mu/2 * q[P-1]^2 + lambdas[idx[P-1]] * q[P-1]) / (P*N)

#define ALM_DELTA 0.1f

static constexpr int MAX_P  = 4096;
static constexpr int JB     = 74;    // j-chunks
static constexpr int JB_MAX = 96;
static constexpr int IT     = 8;     // i-values per thread (register blocking)
static constexpr int BLK    = 128;   // threads per block

// Scratch (allocation-free rule: __device__ globals)
__device__ float g_qpart[JB_MAX * MAX_P];
__device__ float g_q[MAX_P];

// ---------------------------------------------------------------------------
// Kernel 1: pairwise partial sums via sum-of-max identity.
// grid = (ceil(P/(BLK*IT)), JB). Inner loop per pair: FMNMX (alu) + FADD (fma).
// ---------------------------------------------------------------------------
__global__ void k_pairwise(const float* __restrict__ pos,
                           const float* __restrict__ neg,
                           int P, int N, int chunk) {
    extern __shared__ float s_neg[];
    const int jb = blockIdx.y;
    const int j0 = jb * chunk;
    const int cnt = min(chunk, N - j0);          // valid neg count in this chunk
    for (int j = threadIdx.x; j < cnt; j += blockDim.x)
        s_neg[j] = neg[j0 + j];
    __syncthreads();
    if (cnt <= 0) return;

    const int iBase = blockIdx.x * (BLK * IT) + threadIdx.x;

    float t[IT];
    float acc[IT];
    #pragma unroll
    for (int k = 0; k < IT; ++k) {
        const int i = iBase + k * BLK;
        t[k]   = (i < P) ? (pos[i] - ALM_DELTA) : 0.f;
        acc[k] = 0.f;
    }

    int j = 0;
    for (; j + 4 <= cnt; j += 4) {
        #pragma unroll
        for (int u = 0; u < 4; ++u) {
            const float v = s_neg[j + u];
            #pragma unroll
            for (int k = 0; k < IT; ++k)
                acc[k] += fmaxf(v, t[k]);        // FMNMX(alu) + FADD(fma)
        }
    }
    for (; j < cnt; ++j) {
        const float v = s_neg[j];
        #pragma unroll
        for (int k = 0; k < IT; ++k)
            acc[k] += fmaxf(v, t[k]);
    }

    const float fcnt = (float)cnt;
    #pragma unroll
    for (int k = 0; k < IT; ++k) {
        const int i = iBase + k * BLK;
        if (i < P)
            g_qpart[jb * P + i] = acc[k] - fcnt * t[k];
    }
}

// ---------------------------------------------------------------------------
// Kernel 2: reduce JB partials into g_q[i]; copy lambdas -> out.
// ---------------------------------------------------------------------------
__global__ void k_reduce_copy(const float* __restrict__ lambdas,
                              float* __restrict__ out,
                              int P, int L) {
    const int i = blockIdx.x * blockDim.x + threadIdx.x;
    if (i < L) out[i] = lambdas[i];
    if (i < P) {
        float s = 0.f;
        #pragma unroll 8
        for (int jb = 0; jb < JB; ++jb)
            s += g_qpart[jb * P + i];
        g_q[i] = s;
    }
}

// ---------------------------------------------------------------------------
// Kernel 3: scatter-add mu*q into out; last thread writes the loss scalar.
// ---------------------------------------------------------------------------
__global__ void k_scatter_loss(const int* __restrict__ idx,
                               const float* __restrict__ lambdas,
                               const float* __restrict__ mu,
                               float* __restrict__ out,
                               int P, int N, int L, int out_size) {
    const int i = blockIdx.x * blockDim.x + threadIdx.x;
    if (i >= P) return;
    const float m = mu[0];
    atomicAdd(&out[idx[i]], m * g_q[i]);
    if (i == P - 1 && out_size > L) {
        const float q    = g_q[i];
        const float lam  = lambdas[idx[i]];
        const float loss = (0.5f * m * q * q + lam * q) / ((float)P * (float)N);
        out[out_size - 1] = loss;
    }
}

extern "C" void kernel_launch(void* const* d_in, const int* in_sizes, int n_in,
                              void* d_out, int out_size) {
    const float* pos     = (const float*)d_in[0];   // buffer_batch_pos [P]
    const float* neg     = (const float*)d_in[1];   // buffer_batch_neg [N]
    const int*   idx     = (const int*)  d_in[2];   // lambdas_index_buffer [P]
    const float* lambdas = (const float*)d_in[3];   // lambdas [L]
    const float* mu      = (const float*)d_in[4];   // mu [1]
    float* out = (float*)d_out;

    const int P = in_sizes[0];
    const int N = in_sizes[1];
    const int L = in_sizes[3];

    const int chunk   = (N + JB - 1) / JB;                 // 111 for N=8192
    const int iBlocks = (P + BLK * IT - 1) / (BLK * IT);   // 4 for P=4096

    dim3 grid1(iBlocks, JB);                               // 4 x 74 = 296 = 148*2
    k_pairwise<<<grid1, BLK, chunk * sizeof(float)>>>(pos, neg, P, N, chunk);

    const int maxPL = (P > L) ? P : L;
    k_reduce_copy<<<(maxPL + 255) / 256, 256>>>(lambdas, out, P, L);

    k_scatter_loss<<<(P + 255) / 256, 256>>>(idx, lambdas, mu, out, P, N, L, out_size);
}

// round 3
// speedup vs baseline: 1.1800x; 1.1800x over previous
#include <cuda_runtime.h>
#include <cuda_bf16.h>

// q[i] = sum_j relu(neg[j] - pos[i] + DELTA)
//      = sum_j max(neg[j], t_i) - cnt * t_i,   t_i = pos[i] - DELTA   (per chunk)
// out[0..L)       = lambdas, then out[idx[i]] += mu*q[i]  (unique idx)
// out[out_size-1] = (mu/2 * q[P-1]^2 + lambdas[idx[P-1]] * q[P-1]) / (P*N)

#define ALM_DELTA 0.1f

static constexpr int MAX_P  = 4096;
static constexpr int JB     = 74;    // j-chunks
static constexpr int JB_MAX = 96;
static constexpr int CHUNK  = 112;   // multiple of 4 (float4 loads); 74*112 >= 8192
static constexpr int IT     = 4;     // i-values per thread
static constexpr int BLK    = 128;   // threads per block

// Scratch (allocation-free rule: __device__ globals)
__device__ float g_qpart[JB_MAX * MAX_P];
__device__ float g_q[MAX_P];

// ---------------------------------------------------------------------------
// Kernel 1: pairwise partial sums via sum-of-max identity, float4 smem reads.
// grid = (P/(BLK*IT), JB) = (8, 74) = 592 CTAs -> 4 CTAs/SM, 16 warps/SM.
// Inner loop: 1 LDS.128 + 16 FMNMX(alu) + 16 FADD(fma) per 16 pairs.
// ---------------------------------------------------------------------------
__global__ void __launch_bounds__(BLK, 4)
k_pairwise(const float* __restrict__ pos,
           const float* __restrict__ neg,
           int P, int N) {
    __shared__ __align__(16) float s_neg[CHUNK];

    const int jb  = blockIdx.y;
    const int j0  = jb * CHUNK;
    const int cnt = min(CHUNK, N - j0);          // >0, multiple of 4
    for (int j = threadIdx.x; j < cnt; j += BLK)
        s_neg[j] = neg[j0 + j];
    __syncthreads();

    const int iBase = blockIdx.x * (BLK * IT) + threadIdx.x;

    float t[IT], accA[IT], accB[IT];
    #pragma unroll
    for (int k = 0; k < IT; ++k) {
        const int i = iBase + k * BLK;
        t[k]    = (i < P) ? (pos[i] - ALM_DELTA) : 0.f;
        accA[k] = 0.f;
        accB[k] = 0.f;
    }

    const float4* s4 = reinterpret_cast<const float4*>(s_neg);
    const int nv = cnt >> 2;
    #pragma unroll 2
    for (int j = 0; j < nv; ++j) {
        const float4 v = s4[j];
        #pragma unroll
        for (int k = 0; k < IT; ++k) {
            accA[k] += fmaxf(v.x, t[k]);
            accB[k] += fmaxf(v.y, t[k]);
            accA[k] += fmaxf(v.z, t[k]);
            accB[k] += fmaxf(v.w, t[k]);
        }
    }

    const float fcnt = (float)cnt;
    #pragma unroll
    for (int k = 0; k < IT; ++k) {
        const int i = iBase + k * BLK;
        if (i < P)
            g_qpart[jb * P + i] = (accA[k] + accB[k]) - fcnt * t[k];
    }
}

// ---------------------------------------------------------------------------
// Kernel 2: reduce JB partials into g_q[i]; copy lambdas -> out.
// 32 CTAs x 128 threads; per-thread loads are independent (high MLP),
// coalesced across threads.
// ---------------------------------------------------------------------------
__global__ void k_reduce_copy(const float* __restrict__ lambdas,
                              float* __restrict__ out,
                              int P, int L) {
    const int i = blockIdx.x * blockDim.x + threadIdx.x;
    if (i < L) out[i] = lambdas[i];
    if (i < P) {
        float s0 = 0.f, s1 = 0.f;
        #pragma unroll
        for (int jb = 0; jb + 2 <= JB; jb += 2) {
            s0 += g_qpart[jb * P + i];
            s1 += g_qpart[(jb + 1) * P + i];
        }
        if (JB & 1) s0 += g_qpart[(JB - 1) * P + i];
        g_q[i] = s0 + s1;
    }
}

// ---------------------------------------------------------------------------
// Kernel 3: scatter-add mu*q into out; last thread writes the loss scalar.
// ---------------------------------------------------------------------------
__global__ void k_scatter_loss(const int* __restrict__ idx,
                               const float* __restrict__ lambdas,
                               const float* __restrict__ mu,
                               float* __restrict__ out,
                               int P, int N, int L, int out_size) {
    const int i = blockIdx.x * blockDim.x + threadIdx.x;
    if (i >= P) return;
    const float m = mu[0];
    atomicAdd(&out[idx[i]], m * g_q[i]);
    if (i == P - 1 && out_size > L) {
        const float q    = g_q[i];
        const float lam  = lambdas[idx[i]];
        const float loss = (0.5f * m * q * q + lam * q) / ((float)P * (float)N);
        out[out_size - 1] = loss;
    }
}

extern "C" void kernel_launch(void* const* d_in, const int* in_sizes, int n_in,
                              void* d_out, int out_size) {
    const float* pos     = (const float*)d_in[0];   // buffer_batch_pos [P]
    const float* neg     = (const float*)d_in[1];   // buffer_batch_neg [N]
    const int*   idx     = (const int*)  d_in[2];   // lambdas_index_buffer [P]
    const float* lambdas = (const float*)d_in[3];   // lambdas [L]
    const float* mu      = (const float*)d_in[4];   // mu [1]
    float* out = (float*)d_out;

    const int P = in_sizes[0];
    const int N = in_sizes[1];
    const int L = in_sizes[3];

    const int iBlocks = (P + BLK * IT - 1) / (BLK * IT);   // 8 for P=4096
    const int jBlocks = (N + CHUNK - 1) / CHUNK;           // 74 for N=8192

    dim3 grid1(iBlocks, jBlocks);                          // 8 x 74 = 592
    k_pairwise<<<grid1, BLK>>>(pos, neg, P, N);

    const int maxPL = (P > L) ? P : L;
    k_reduce_copy<<<(maxPL + 127) / 128, 128>>>(lambdas, out, P, L);

    k_scatter_loss<<<(P + 255) / 256, 256>>>(idx, lambdas, mu, out, P, N, L, out_size);
}